// round 7
// baseline (speedup 1.0000x reference)
#include <cuda_runtime.h>
#include <cuda_bf16.h>

#define T_STEPS 16384
#define D_IN    512
#define H_DIM   1024
#define O_DIM   512

// Recurrence: 64 CTAs x 256 threads (8 warps), 2 rows per warp -> 16 rows/CTA.
#define NCTA     64
#define NTHREADS 256

__device__ float    g_hs[T_STEPS * H_DIM];   // full history (exchange + GEMM input)
__device__ unsigned g_flag[NCTA];            // per-CTA step flags (reset each run)
__device__ unsigned g_done;                  // exit counter (reset each run)

__device__ __forceinline__ float fast_tanh(float x) {
    float e = __expf(2.0f * x);
    return 1.0f - __fdividef(2.0f, e + 1.0f);
}

__device__ __forceinline__ unsigned ld_acq(const unsigned* p) {
    unsigned v;
    asm volatile("ld.acquire.gpu.global.u32 %0, [%1];" : "=r"(v) : "l"(p) : "memory");
    return v;
}
__device__ __forceinline__ void st_rel(unsigned* p, unsigned v) {
    asm volatile("st.release.gpu.global.u32 [%0], %1;" :: "l"(p), "r"(v) : "memory");
}

__global__ __launch_bounds__(NTHREADS, 1)
void rnn_kernel(const int* __restrict__ inputs,
                const float* __restrict__ h0,
                const float* __restrict__ U,
                const float* __restrict__ W,
                const float* __restrict__ bh,
                float* __restrict__ out_hT)
{
    extern __shared__ int sIn[];             // 16384 tokens: 64 KB dynamic
    __shared__ float hs_s[H_DIM];            // staged previous hidden state: 4 KB

    const int tid  = threadIdx.x;
    const int lane = tid & 31;
    const int warp = tid >> 5;
    const int rowbase = blockIdx.x * 16 + warp * 2;
    const int myrow = rowbase + lane;        // valid for lane < 2

    // Stage token sequence
    for (int i = tid; i < T_STEPS; i += NTHREADS) sIn[i] = inputs[i];

    // Register-resident W: 2 rows per warp, 32 cols per lane.
    float w0[32], w1[32];
    {
        const float* W0 = W + (size_t)rowbase * H_DIM;
        const float* W1 = W + (size_t)(rowbase + 1) * H_DIM;
#pragma unroll
        for (int j = 0; j < 8; j++) {
            float4 a = *(const float4*)&W0[j * 128 + lane * 4];
            w0[j*4+0] = a.x; w0[j*4+1] = a.y; w0[j*4+2] = a.z; w0[j*4+3] = a.w;
            float4 b = *(const float4*)&W1[j * 128 + lane * 4];
            w1[j*4+0] = b.x; w1[j*4+1] = b.y; w1[j*4+2] = b.z; w1[j*4+3] = b.w;
        }
    }

    float bias = 0.0f, ux = 0.0f;
    __syncthreads();                         // sIn ready
    if (lane < 2) {
        bias = bh[myrow];
        ux = U[(size_t)myrow * D_IN + sIn[0]];
    }

    for (int t = 0; t < T_STEPS; t++) {
        // ---- wait for h_{t-1} to be fully published (distributed flags) ----
        if (t > 0) {
            if (tid < NCTA) {
                const unsigned target = (unsigned)t;
                while (ld_acq(&g_flag[tid]) < target) { }
            }
            __syncthreads();                 // acquire hb extends to all threads
        }

        // ---- stage h_{t-1} into smem (fresh addresses each step: L1-safe) ----
        const float* hprev = (t == 0) ? h0 : (g_hs + (size_t)(t - 1) * H_DIM);
        float4 hv4 = *(const float4*)&hprev[tid * 4];
        *(float4*)&hs_s[tid * 4] = hv4;

        // Prefetch next ux while staging drains
        float ux_next = 0.0f;
        if (lane < 2 && t + 1 < T_STEPS)
            ux_next = U[(size_t)myrow * D_IN + sIn[t + 1]];

        __syncthreads();                     // hs_s fully staged

        // ---- dot: 2 rows, 2 accumulator chains each ----
        float a00 = 0.f, a01 = 0.f, a10 = 0.f, a11 = 0.f;
#pragma unroll
        for (int j = 0; j < 8; j++) {
            float4 hv = *(const float4*)&hs_s[j * 128 + lane * 4];
            a00 += w0[j*4+0] * hv.x;  a01 += w0[j*4+1] * hv.y;
            a00 += w0[j*4+2] * hv.z;  a01 += w0[j*4+3] * hv.w;
            a10 += w1[j*4+0] * hv.x;  a11 += w1[j*4+1] * hv.y;
            a10 += w1[j*4+2] * hv.z;  a11 += w1[j*4+3] * hv.w;
        }
        float r0 = a00 + a01;
        float r1 = a10 + a11;
#pragma unroll
        for (int s = 16; s > 0; s >>= 1) {
            r0 += __shfl_xor_sync(0xffffffffu, r0, s);
            r1 += __shfl_xor_sync(0xffffffffu, r1, s);
        }

        if (lane < 2) {
            float pre = ((lane == 0) ? r0 : r1) + ux + bias;
            g_hs[(size_t)t * H_DIM + myrow] = fast_tanh(pre);
        }
        ux = ux_next;

        __syncthreads();                     // all 16 rows of this CTA published

        // ---- release this CTA's flag (skip at last step: nobody consumes,
        //      and skipping lets the epilogue reset flags race-free) ----
        if (t < T_STEPS - 1 && tid == 0)
            st_rel(&g_flag[blockIdx.x], (unsigned)(t + 1));
    }

    // ---- exit dance (proven in round 2): done counter + reset for replays ----
    if (tid == 0) {
        asm volatile("red.release.gpu.global.add.u32 [%0], %1;"
                     :: "l"(&g_done), "r"(1u) : "memory");
    }
    if (blockIdx.x == 0) {
        if (tid == 0) {
            while (ld_acq(&g_done) < (unsigned)NCTA) { }
        }
        __syncthreads();                     // all CTAs' final h writes visible
        if (tid < NCTA) g_flag[tid] = 0u;    // reset for next graph replay
        if (tid == 0)   g_done = 0u;
        for (int i = tid; i < H_DIM; i += NTHREADS)
            out_hT[i] = g_hs[(size_t)(T_STEPS - 1) * H_DIM + i];
    }
}

// ---------------------------------------------------------------------------
// logits = hs @ V^T + by : C[16384 x 512] = A[16384 x 1024] * V[512 x 1024]^T
// 128x64x16 tiles, 256 threads, 8x4 register microtiles. (proven, 412us)
// ---------------------------------------------------------------------------
#define BM 128
#define BN 64
#define BK 16

__global__ __launch_bounds__(256)
void gemm_kernel(const float* __restrict__ A,
                 const float* __restrict__ V,
                 const float* __restrict__ by,
                 float* __restrict__ C)
{
    __shared__ float As[BK][BM + 4];
    __shared__ float Bs[BK][BN + 4];

    const int tid = threadIdx.x;
    const int bm  = blockIdx.y * BM;
    const int bn  = blockIdx.x * BN;
    const int tx  = tid & 15;
    const int ty  = tid >> 4;

    const int ar = tid >> 1;
    const int ak = (tid & 1) * 8;
    const int br = tid >> 2;
    const int bk = (tid & 3) * 4;

    float acc[8][4];
#pragma unroll
    for (int i = 0; i < 8; i++)
#pragma unroll
        for (int j = 0; j < 4; j++) acc[i][j] = 0.f;

    for (int kt = 0; kt < H_DIM; kt += BK) {
        float4 a0 = *(const float4*)&A[(size_t)(bm + ar) * H_DIM + kt + ak];
        float4 a1 = *(const float4*)&A[(size_t)(bm + ar) * H_DIM + kt + ak + 4];
        float4 bv = *(const float4*)&V[(size_t)(bn + br) * H_DIM + kt + bk];
        As[ak + 0][ar] = a0.x; As[ak + 1][ar] = a0.y;
        As[ak + 2][ar] = a0.z; As[ak + 3][ar] = a0.w;
        As[ak + 4][ar] = a1.x; As[ak + 5][ar] = a1.y;
        As[ak + 6][ar] = a1.z; As[ak + 7][ar] = a1.w;
        Bs[bk + 0][br] = bv.x; Bs[bk + 1][br] = bv.y;
        Bs[bk + 2][br] = bv.z; Bs[bk + 3][br] = bv.w;
        __syncthreads();

#pragma unroll
        for (int k = 0; k < BK; k++) {
            float4 rb  = *(const float4*)&Bs[k][tx * 4];
            float4 ra0 = *(const float4*)&As[k][ty * 8];
            float4 ra1 = *(const float4*)&As[k][ty * 8 + 4];
            float ra[8]  = {ra0.x, ra0.y, ra0.z, ra0.w, ra1.x, ra1.y, ra1.z, ra1.w};
            float rbb[4] = {rb.x, rb.y, rb.z, rb.w};
#pragma unroll
            for (int i = 0; i < 8; i++)
#pragma unroll
                for (int j = 0; j < 4; j++)
                    acc[i][j] += ra[i] * rbb[j];
        }
        __syncthreads();
    }

    const float4 byv = *(const float4*)&by[bn + tx * 4];
    const float bb[4] = {byv.x, byv.y, byv.z, byv.w};
#pragma unroll
    for (int i = 0; i < 8; i++) {
        float4 o;
        o.x = acc[i][0] + bb[0];
        o.y = acc[i][1] + bb[1];
        o.z = acc[i][2] + bb[2];
        o.w = acc[i][3] + bb[3];
        *(float4*)&C[(size_t)(bm + ty * 8 + i) * O_DIM + bn + tx * 4] = o;
    }
}

extern "C" void kernel_launch(void* const* d_in, const int* in_sizes, int n_in,
                              void* d_out, int out_size)
{
    (void)in_sizes; (void)n_in; (void)out_size;
    const int*   inputs = (const int*)  d_in[0];
    const float* h0     = (const float*)d_in[1];
    const float* U      = (const float*)d_in[2];
    const float* W      = (const float*)d_in[3];
    const float* V      = (const float*)d_in[4];
    const float* bh     = (const float*)d_in[5];
    const float* by     = (const float*)d_in[6];

    float* logits = (float*)d_out;
    float* out_hT = (float*)d_out + (size_t)T_STEPS * O_DIM;

    cudaFuncSetAttribute(rnn_kernel,
                         cudaFuncAttributeMaxDynamicSharedMemorySize,
                         T_STEPS * (int)sizeof(int));

    rnn_kernel<<<NCTA, NTHREADS, T_STEPS * sizeof(int)>>>(inputs, h0, U, W, bh, out_hT);

    static float* hs_ptr = nullptr;
    if (!hs_ptr) { void* p = nullptr; cudaGetSymbolAddress(&p, g_hs); hs_ptr = (float*)p; }

    dim3 ggrid(O_DIM / BN, T_STEPS / BM);
    gemm_kernel<<<ggrid, 256>>>(hs_ptr, V, by, logits);
}

// round 8
// speedup vs baseline: 1.5187x; 1.5187x over previous
#include <cuda_runtime.h>
#include <cuda_bf16.h>

#define T_STEPS 16384
#define D_IN    512
#define H_DIM   1024
#define O_DIM   512

// Recurrence: 64 CTAs x 256 threads (8 warps), 2 rows per warp -> 16 rows/CTA.
#define NCTA     64
#define NTHREADS 256

__device__ float    g_hs[T_STEPS * H_DIM];   // full history (exchange + GEMM input)
__device__ unsigned g_count;                 // step barrier counter (self-resetting)
__device__ unsigned g_done;                  // exit counter (self-resetting)

__device__ __forceinline__ float fast_tanh(float x) {
    float e = __expf(2.0f * x);
    return 1.0f - __fdividef(2.0f, e + 1.0f);
}

__device__ __forceinline__ unsigned ld_acq(const unsigned* p) {
    unsigned v;
    asm volatile("ld.acquire.gpu.global.u32 %0, [%1];" : "=r"(v) : "l"(p) : "memory");
    return v;
}

// packed 2x fp32 fma: acc += a * b (elementwise on packed pairs)
__device__ __forceinline__ void fma2(unsigned long long& acc,
                                     unsigned long long a, unsigned long long b) {
    asm("fma.rn.f32x2 %0, %1, %2, %0;" : "+l"(acc) : "l"(a), "l"(b));
}
__device__ __forceinline__ float2 unpack2(unsigned long long v) {
    float2 r;
    asm("mov.b64 {%0, %1}, %2;" : "=f"(r.x), "=f"(r.y) : "l"(v));
    return r;
}

__global__ __launch_bounds__(NTHREADS, 1)
void rnn_kernel(const int* __restrict__ inputs,
                const float* __restrict__ h0,
                const float* __restrict__ U,
                const float* __restrict__ W,
                const float* __restrict__ bh,
                float* __restrict__ out_hT)
{
    extern __shared__ int sIn[];             // 16384 tokens: 64 KB dynamic
    __shared__ float hs_s[H_DIM];            // staged previous hidden state: 4 KB

    const int tid  = threadIdx.x;
    const int lane = tid & 31;
    const int warp = tid >> 5;
    const int rowbase = blockIdx.x * 16 + warp * 2;
    const int myrow = rowbase + lane;        // valid for lane < 2

    // Stage token sequence
    for (int i = tid; i < T_STEPS; i += NTHREADS) sIn[i] = inputs[i];

    // Register-resident W, packed as fp32 pairs for f32x2 FMA.
    // w0p[j*2+c] holds W[row][j*128 + lane*4 + 2c .. +2c+1]
    unsigned long long w0p[16], w1p[16];
    {
        const float* W0 = W + (size_t)rowbase * H_DIM;
        const float* W1 = W + (size_t)(rowbase + 1) * H_DIM;
#pragma unroll
        for (int j = 0; j < 8; j++) {
            ulonglong2 a = *(const ulonglong2*)&W0[j * 128 + lane * 4];
            w0p[j*2+0] = a.x; w0p[j*2+1] = a.y;
            ulonglong2 b = *(const ulonglong2*)&W1[j * 128 + lane * 4];
            w1p[j*2+0] = b.x; w1p[j*2+1] = b.y;
        }
    }

    float bias = 0.0f, ux = 0.0f;
    __syncthreads();                         // sIn ready
    if (lane < 2) {
        bias = bh[myrow];
        ux = U[(size_t)myrow * D_IN + sIn[0]];
    }

    for (int t = 0; t < T_STEPS; t++) {
        // ---- stage h_{t-1} into smem (fresh address each step: L1-safe) ----
        const float* hprev = (t == 0) ? h0 : (g_hs + (size_t)(t - 1) * H_DIM);
        float4 hv4 = *(const float4*)&hprev[tid * 4];
        *(float4*)&hs_s[tid * 4] = hv4;

        // Prefetch next ux while staging drains
        float ux_next = 0.0f;
        if (lane < 2 && t + 1 < T_STEPS)
            ux_next = U[(size_t)myrow * D_IN + sIn[t + 1]];

        __syncthreads();                     // hs_s fully staged

        // ---- dot: 2 rows, packed f32x2 accumulators ----
        unsigned long long a00 = 0ull, a01 = 0ull, a10 = 0ull, a11 = 0ull;
#pragma unroll
        for (int j = 0; j < 8; j++) {
            ulonglong2 hv = *(const ulonglong2*)&hs_s[j * 128 + lane * 4];
            fma2(a00, w0p[j*2+0], hv.x);
            fma2(a01, w0p[j*2+1], hv.y);
            fma2(a10, w1p[j*2+0], hv.x);
            fma2(a11, w1p[j*2+1], hv.y);
        }
        float2 u00 = unpack2(a00), u01 = unpack2(a01);
        float2 u10 = unpack2(a10), u11 = unpack2(a11);
        float r0 = (u00.x + u00.y) + (u01.x + u01.y);
        float r1 = (u10.x + u10.y) + (u11.x + u11.y);

        // Two interleaved butterfly reductions
#pragma unroll
        for (int s = 16; s > 0; s >>= 1) {
            r0 += __shfl_xor_sync(0xffffffffu, r0, s);
            r1 += __shfl_xor_sync(0xffffffffu, r1, s);
        }

        if (lane < 2) {
            float pre = ((lane == 0) ? r0 : r1) + ux + bias;
            g_hs[(size_t)t * H_DIM + myrow] = fast_tanh(pre);
        }
        ux = ux_next;

        // ---- lean grid barrier: release-RED + pipelined acquire-poll ----
        if (t < T_STEPS - 1) {
            __syncthreads();                 // all 16 rows published (block scope)
            if (tid == 0) {
                asm volatile("red.release.gpu.global.add.u32 [%0], %1;"
                             :: "l"(&g_count), "r"(1u) : "memory");
                const unsigned target = (unsigned)(t + 1) * NCTA;
                // 2-deep pipelined poll: halves detection granularity
                unsigned a = ld_acq(&g_count);
                unsigned b = ld_acq(&g_count);
                while (a < target) {
                    a = b;
                    b = ld_acq(&g_count);
                }
            }
            __syncthreads();                 // release workers
        }
    }

    // ---- exit dance (proven): done counter + reset for graph replays ----
    __syncthreads();
    if (tid == 0) {
        asm volatile("red.release.gpu.global.add.u32 [%0], %1;"
                     :: "l"(&g_done), "r"(1u) : "memory");
    }
    if (blockIdx.x == 0) {
        if (tid == 0) {
            while (ld_acq(&g_done) < (unsigned)NCTA) { }
            g_count = 0u;                    // no CTA reads these anymore
            g_done  = 0u;
        }
        __syncthreads();
        for (int i = tid; i < H_DIM; i += NTHREADS)
            out_hT[i] = g_hs[(size_t)(T_STEPS - 1) * H_DIM + i];
    }
}

// ---------------------------------------------------------------------------
// logits = hs @ V^T + by : C[16384 x 512] = A[16384 x 1024] * V[512 x 1024]^T
// 128x64x16 tiles, 256 threads, 8x4 register microtiles. (proven, 412us)
// ---------------------------------------------------------------------------
#define BM 128
#define BN 64
#define BK 16

__global__ __launch_bounds__(256)
void gemm_kernel(const float* __restrict__ A,
                 const float* __restrict__ V,
                 const float* __restrict__ by,
                 float* __restrict__ C)
{
    __shared__ float As[BK][BM + 4];
    __shared__ float Bs[BK][BN + 4];

    const int tid = threadIdx.x;
    const int bm  = blockIdx.y * BM;
    const int bn  = blockIdx.x * BN;
    const int tx  = tid & 15;
    const int ty  = tid >> 4;

    const int ar = tid >> 1;
    const int ak = (tid & 1) * 8;
    const int br = tid >> 2;
    const int bk = (tid & 3) * 4;

    float acc[8][4];
#pragma unroll
    for (int i = 0; i < 8; i++)
#pragma unroll
        for (int j = 0; j < 4; j++) acc[i][j] = 0.f;

    for (int kt = 0; kt < H_DIM; kt += BK) {
        float4 a0 = *(const float4*)&A[(size_t)(bm + ar) * H_DIM + kt + ak];
        float4 a1 = *(const float4*)&A[(size_t)(bm + ar) * H_DIM + kt + ak + 4];
        float4 bv = *(const float4*)&V[(size_t)(bn + br) * H_DIM + kt + bk];
        As[ak + 0][ar] = a0.x; As[ak + 1][ar] = a0.y;
        As[ak + 2][ar] = a0.z; As[ak + 3][ar] = a0.w;
        As[ak + 4][ar] = a1.x; As[ak + 5][ar] = a1.y;
        As[ak + 6][ar] = a1.z; As[ak + 7][ar] = a1.w;
        Bs[bk + 0][br] = bv.x; Bs[bk + 1][br] = bv.y;
        Bs[bk + 2][br] = bv.z; Bs[bk + 3][br] = bv.w;
        __syncthreads();

#pragma unroll
        for (int k = 0; k < BK; k++) {
            float4 rb  = *(const float4*)&Bs[k][tx * 4];
            float4 ra0 = *(const float4*)&As[k][ty * 8];
            float4 ra1 = *(const float4*)&As[k][ty * 8 + 4];
            float ra[8]  = {ra0.x, ra0.y, ra0.z, ra0.w, ra1.x, ra1.y, ra1.z, ra1.w};
            float rbb[4] = {rb.x, rb.y, rb.z, rb.w};
#pragma unroll
            for (int i = 0; i < 8; i++)
#pragma unroll
                for (int j = 0; j < 4; j++)
                    acc[i][j] += ra[i] * rbb[j];
        }
        __syncthreads();
    }

    const float4 byv = *(const float4*)&by[bn + tx * 4];
    const float bb[4] = {byv.x, byv.y, byv.z, byv.w};
#pragma unroll
    for (int i = 0; i < 8; i++) {
        float4 o;
        o.x = acc[i][0] + bb[0];
        o.y = acc[i][1] + bb[1];
        o.z = acc[i][2] + bb[2];
        o.w = acc[i][3] + bb[3];
        *(float4*)&C[(size_t)(bm + ty * 8 + i) * O_DIM + bn + tx * 4] = o;
    }
}

extern "C" void kernel_launch(void* const* d_in, const int* in_sizes, int n_in,
                              void* d_out, int out_size)
{
    (void)in_sizes; (void)n_in; (void)out_size;
    const int*   inputs = (const int*)  d_in[0];
    const float* h0     = (const float*)d_in[1];
    const float* U      = (const float*)d_in[2];
    const float* W      = (const float*)d_in[3];
    const float* V      = (const float*)d_in[4];
    const float* bh     = (const float*)d_in[5];
    const float* by     = (const float*)d_in[6];

    float* logits = (float*)d_out;
    float* out_hT = (float*)d_out + (size_t)T_STEPS * O_DIM;

    cudaFuncSetAttribute(rnn_kernel,
                         cudaFuncAttributeMaxDynamicSharedMemorySize,
                         T_STEPS * (int)sizeof(int));

    rnn_kernel<<<NCTA, NTHREADS, T_STEPS * sizeof(int)>>>(inputs, h0, U, W, bh, out_hT);

    static float* hs_ptr = nullptr;
    if (!hs_ptr) { void* p = nullptr; cudaGetSymbolAddress(&p, g_hs); hs_ptr = (float*)p; }

    dim3 ggrid(O_DIM / BN, T_STEPS / BM);
    gemm_kernel<<<ggrid, 256>>>(hs_ptr, V, by, logits);
}